// round 14
// baseline (speedup 1.0000x reference)
#include <cuda_runtime.h>
#include <cuda_fp16.h>
#include <math.h>
#include <stdint.h>

#define BATCH 32
#define SEQ   2048
#define DIM   1024

#define BM 64                       // l-rows per block
#define BNP 128                     // n per pass
#define NPASS 8                     // 8 passes cover D=1024
#define BKH 64                      // k halfs per chunk (128 B)
#define KCHUNKS 16                  // full K resident
#define ROWH 72                     // halfs per smem row (LDSM conflict-free)

#define A_CHUNK (BM * ROWH * 2)     // 9216 B
#define B_STAGE (BNP * ROWH * 2)    // 18432 B
#define OFF_A(kc) ((kc) * A_CHUNK)                       // 16 x 9216 = 147456
#define OFF_B(s)  (KCHUNKS * A_CHUNK + (s) * B_STAGE)    // +3 x 18432
#define OFF_Q     (KCHUNKS * A_CHUNK + 3 * B_STAGE)      // 202752
#define OFF_V     (OFF_Q + DIM * 4)
#define OFF_SC    (OFF_V + DIM * 4)
#define SMEM_BYTES (OFF_SC + BM * 4)                     // 211200 B

// Scratch (static __device__ — no allocation inside kernel_launch)
__device__ float  g_q[BATCH * DIM];
__device__ float  g_scores[BATCH * SEQ];
__device__ __half g_enc_h[(size_t)BATCH * SEQ * DIM];   // written by score pass 0
__device__ __half g_U_h[DIM * DIM];                     // fp16 copy of Uw (prep)

__device__ __forceinline__ uint32_t smem_u32(const void* p) {
    uint32_t a;
    asm("{ .reg .u64 t; cvta.to.shared.u64 t, %1; cvt.u32.u64 %0, t; }"
        : "=r"(a) : "l"(p));
    return a;
}

__device__ __forceinline__ void cp16(uint32_t dst, const void* src) {
    asm volatile("cp.async.cg.shared.global [%0], [%1], 16;"
                 :: "r"(dst), "l"(src) : "memory");
}
#define CP_COMMIT() asm volatile("cp.async.commit_group;" ::: "memory")
#define CP_WAIT(n)  asm volatile("cp.async.wait_group %0;" :: "n"(n) : "memory")

__device__ __forceinline__ void ldm_x4(uint32_t r[4], uint32_t addr) {
    asm volatile("ldmatrix.sync.aligned.m8n8.x4.shared.b16 {%0,%1,%2,%3}, [%4];"
                 : "=r"(r[0]), "=r"(r[1]), "=r"(r[2]), "=r"(r[3]) : "r"(addr));
}

__device__ __forceinline__ void mma_f16(float c[4], const uint32_t a[4], const uint32_t b[2]) {
    asm volatile(
        "mma.sync.aligned.m16n8k16.row.col.f32.f16.f16.f32 "
        "{%0,%1,%2,%3}, {%4,%5,%6,%7}, {%8,%9}, {%0,%1,%2,%3};"
        : "+f"(c[0]), "+f"(c[1]), "+f"(c[2]), "+f"(c[3])
        : "r"(a[0]), "r"(a[1]), "r"(a[2]), "r"(a[3]), "r"(b[0]), "r"(b[1]));
}

// ---------------------------------------------------------------------------
// Kernel 0 (tiny prep): U fp32->fp16 + q' projection.
// ---------------------------------------------------------------------------
#define NU8 ((size_t)DIM * DIM / 8)                    // 131072
#define NUCONV_BLOCKS ((unsigned)((NU8 + 255) / 256))  // 512
#define NQP_BLOCKS    (BATCH * DIM / 8)                // 4096

__global__ void prep_kernel(const float* __restrict__ Uw,
                            const float* __restrict__ dh,
                            const float* __restrict__ Ww,
                            const float* __restrict__ Wb,
                            const float* __restrict__ Ub) {
    if (blockIdx.x < NUCONV_BLOCKS) {
        size_t k = (size_t)blockIdx.x * 256 + threadIdx.x;
        if (k >= NU8) return;
        const float4* src = (const float4*)Uw;
        float4 f0 = src[k * 2], f1 = src[k * 2 + 1];
        __half2 h[4];
        h[0] = __floats2half2_rn(f0.x, f0.y);
        h[1] = __floats2half2_rn(f0.z, f0.w);
        h[2] = __floats2half2_rn(f1.x, f1.y);
        h[3] = __floats2half2_rn(f1.z, f1.w);
        ((uint4*)g_U_h)[k] = *(uint4*)h;
        return;
    }
    int qgid = (int)(blockIdx.x - NUCONV_BLOCKS) * 256 + threadIdx.x;
    int warp = qgid >> 5;
    int lane = threadIdx.x & 31;
    if (warp >= BATCH * DIM) return;
    int b = warp / DIM, d = warp % DIM;
    const float* x = dh + b * DIM;
    const float* w = Ww + (size_t)d * DIM;
    float s = 0.f;
    #pragma unroll 4
    for (int e = lane; e < DIM; e += 32) s += x[e] * w[e];
    #pragma unroll
    for (int o = 16; o; o >>= 1) s += __shfl_xor_sync(0xffffffffu, s, o);
    if (lane == 0) g_q[warp] = s + Wb[d] + Ub[d];
}

// ---------------------------------------------------------------------------
// Kernel 2 (dominant): one block owns a full (b, 64-l-row) tile across ALL of
// D. A (enc fp32) is read ONCE, converted in-kernel to a resident full-K fp16
// smem tile (pass 0), and STG'd to g_enc_h for the context kernel (free:
// DRAM idle during compute). B (U fp16) streams L2->smem, 3-stage cp.async.
// 8 n-passes of 128; per-pass fused tanh*v epilogue into smem score partials
// (no global atomics). Grid (32, 32) = 1024 blocks, 256 threads, 1 CTA/SM.
// Warps: 2m x 4n, warp tile 32x32.
// ---------------------------------------------------------------------------
__global__ __launch_bounds__(256, 1)
void score_kernel(const float* __restrict__ enc,
                  const float* __restrict__ vw) {
    extern __shared__ char smc[];
    const uint32_t sb = smem_u32(smc);

    const int tid  = threadIdx.x;
    const int wid  = tid >> 5;
    const int lane = tid & 31;
    const int wm   = wid >> 2;         // 0..1 -> m offset wm*32
    const int wn   = wid & 3;          // 0..3 -> n offset wn*32
    const int gr   = lane >> 2;
    const int gc   = lane & 3;

    const int l0 = blockIdx.x * BM;
    const int b  = blockIdx.y;

    float* q_sh = (float*)(smc + OFF_Q);
    float* v_sh = (float*)(smc + OFF_V);
    float* score_sm = (float*)(smc + OFF_SC);
    for (int i = tid; i < DIM; i += 256) {
        q_sh[i] = g_q[b * DIM + i];
        v_sh[i] = vw[i];
    }
    if (tid < BM) score_sm[tid] = 0.f;

    // A conversion mapping: 4 threads/row, 16 floats each
    const int crowA = tid >> 2;          // 0..63
    const int csegA = (tid & 3) * 16;
    const float* Aenc = enc + ((size_t)(b * SEQ + l0 + crowA)) * DIM + csegA;
    __half* EncOut = g_enc_h + ((size_t)(b * SEQ + l0 + crowA)) * DIM + csegA;
    const uint32_t aStsOff = (crowA * ROWH + csegA) * 2;

    // B cp.async mapping: 32 rows/pass x 8 segs, 4 passes
    const int browB = tid >> 3;          // 0..31
    const int bsegB = (tid & 7) * 8;

    uint32_t a16[8];
    float4 vld[4];

    // ---- prologue ----
    // A chunk 0: LDG -> cvt -> STS A16[0] + STG enc_h
    #pragma unroll
    for (int j = 0; j < 4; j++) vld[j] = *(const float4*)(Aenc + j * 4);
    #pragma unroll
    for (int j = 0; j < 4; j++) {
        __half2 h0 = __floats2half2_rn(vld[j].x, vld[j].y);
        __half2 h1 = __floats2half2_rn(vld[j].z, vld[j].w);
        a16[j * 2] = *(uint32_t*)&h0; a16[j * 2 + 1] = *(uint32_t*)&h1;
    }
    {
        uint4* d = (uint4*)(smc + OFF_A(0) + aStsOff);
        d[0] = *(uint4*)&a16[0]; d[1] = *(uint4*)&a16[4];
        ((uint4*)EncOut)[0] = *(uint4*)&a16[0];
        ((uint4*)EncOut)[1] = *(uint4*)&a16[4];
    }
    // A chunk 1: LDG -> cvt -> hold (STS at iter 0) + STG
    #pragma unroll
    for (int j = 0; j < 4; j++) vld[j] = *(const float4*)(Aenc + BKH + j * 4);
    #pragma unroll
    for (int j = 0; j < 4; j++) {
        __half2 h0 = __floats2half2_rn(vld[j].x, vld[j].y);
        __half2 h1 = __floats2half2_rn(vld[j].z, vld[j].w);
        a16[j * 2] = *(uint32_t*)&h0; a16[j * 2 + 1] = *(uint32_t*)&h1;
    }
    ((uint4*)(EncOut + BKH))[0] = *(uint4*)&a16[0];
    ((uint4*)(EncOut + BKH))[1] = *(uint4*)&a16[4];

    // B chunks cp=0,1 (pass 0, k=0,1)
    #pragma unroll
    for (int g = 0; g < 2; g++) {
        const uint32_t bst = sb + OFF_B(g);
        #pragma unroll
        for (int r = 0; r < 4; r++) {
            int row = browB + r * 32;
            cp16(bst + (row * ROWH + bsegB) * 2,
                 g_U_h + (size_t)row * DIM + g * BKH + bsegB);
        }
        CP_COMMIT();
    }

    // ldmatrix lane address components
    const int a_row = (lane & 7) + ((lane >> 3) & 1) * 8;
    const int a_col = ((lane >> 4) & 1) * 8;
    const int b_row = (lane & 7) + ((lane >> 4) & 1) * 8;
    const int b_col = ((lane >> 3) & 1) * 8;

    float acc[2][4][4];
    #pragma unroll
    for (int i = 0; i < 2; i++)
        #pragma unroll
        for (int j = 0; j < 4; j++)
            #pragma unroll
            for (int r = 0; r < 4; r++) acc[i][j][r] = 0.f;

    // ================= pass 0 (with A conversion) =================
    for (int kc = 0; kc < KCHUNKS; kc++) {
        CP_WAIT(1);
        __syncthreads();

        // STS pending fp16 chunk kc+1 into resident slot
        if (kc + 1 < KCHUNKS) {
            uint4* d = (uint4*)(smc + OFF_A(kc + 1) + aStsOff);
            d[0] = *(uint4*)&a16[0]; d[1] = *(uint4*)&a16[4];
        }
        // LDG A chunk kc+2 (converted after the mma below)
        const int kn = kc + 2;
        if (kn < KCHUNKS) {
            const float* src = Aenc + kn * BKH;
            #pragma unroll
            for (int j = 0; j < 4; j++) vld[j] = *(const float4*)(src + j * 4);
        }
        // B prefetch for global chunk cp2 = kc+2 (maps into pass 1 at the end)
        {
            const int cp2 = kc + 2;
            const int p2 = cp2 >> 4, k2 = cp2 & 15;
            const uint32_t bst = sb + OFF_B(cp2 % 3);
            #pragma unroll
            for (int r = 0; r < 4; r++) {
                int row = browB + r * 32;
                cp16(bst + (row * ROWH + bsegB) * 2,
                     g_U_h + (size_t)(p2 * BNP + row) * DIM + k2 * BKH + bsegB);
            }
        }
        CP_COMMIT();

        // mma on chunk kc: A16[kc] resident, B stage kc%3
        const uint32_t aba = sb + OFF_A(kc) + ((wm * 32 + a_row) * ROWH + a_col) * 2;
        const uint32_t bba = sb + OFF_B(kc % 3) + ((wn * 32 + b_row) * ROWH + b_col) * 2;
        #pragma unroll
        for (int ks = 0; ks < 4; ks++) {
            const int kb = ks * 16;
            uint32_t af[2][4], bq[2][4];
            #pragma unroll
            for (int p = 0; p < 2; p++)
                ldm_x4(bq[p], bba + (p * 16 * ROWH + kb) * 2);
            #pragma unroll
            for (int i = 0; i < 2; i++)
                ldm_x4(af[i], aba + (i * 16 * ROWH + kb) * 2);
            #pragma unroll
            for (int i = 0; i < 2; i++)
                #pragma unroll
                for (int j = 0; j < 4; j++)
                    mma_f16(acc[i][j], af[i], &bq[j >> 1][(j & 1) * 2]);
        }

        // convert chunk kc+2 (LDG latency drained by the mma block) + STG
        if (kn < KCHUNKS) {
            #pragma unroll
            for (int j = 0; j < 4; j++) {
                __half2 h0 = __floats2half2_rn(vld[j].x, vld[j].y);
                __half2 h1 = __floats2half2_rn(vld[j].z, vld[j].w);
                a16[j * 2] = *(uint32_t*)&h0; a16[j * 2 + 1] = *(uint32_t*)&h1;
            }
            ((uint4*)(EncOut + kn * BKH))[0] = *(uint4*)&a16[0];
            ((uint4*)(EncOut + kn * BKH))[1] = *(uint4*)&a16[4];
        }
    }
    // pass 0 epilogue
    #pragma unroll
    for (int i = 0; i < 2; i++) {
        float slo = 0.f, shi = 0.f;
        #pragma unroll
        for (int j = 0; j < 4; j++) {
            const int c = wn * 32 + j * 8 + gc * 2;   // pass 0: global n = c
            const float v0 = v_sh[c], v1 = v_sh[c + 1];
            const float q0 = q_sh[c], q1 = q_sh[c + 1];
            float x0 = q0 + acc[i][j][0], x1 = q1 + acc[i][j][1];
            float x2 = q0 + acc[i][j][2], x3 = q1 + acc[i][j][3];
            slo += v0 * (1.f - 2.f / (__expf(2.f * x0) + 1.f))
                 + v1 * (1.f - 2.f / (__expf(2.f * x1) + 1.f));
            shi += v0 * (1.f - 2.f / (__expf(2.f * x2) + 1.f))
                 + v1 * (1.f - 2.f / (__expf(2.f * x3) + 1.f));
            #pragma unroll
            for (int r = 0; r < 4; r++) acc[i][j][r] = 0.f;
        }
        slo += __shfl_xor_sync(0xffffffffu, slo, 1);
        slo += __shfl_xor_sync(0xffffffffu, slo, 2);
        shi += __shfl_xor_sync(0xffffffffu, shi, 1);
        shi += __shfl_xor_sync(0xffffffffu, shi, 2);
        if (gc == 0) {
            atomicAdd(&score_sm[wm * 32 + i * 16 + gr], slo);
            atomicAdd(&score_sm[wm * 32 + i * 16 + gr + 8], shi);
        }
    }

    // ================= passes 1..7 (A resident, lean loop) =================
    for (int pass = 1; pass < NPASS; pass++) {
        for (int kc = 0; kc < KCHUNKS; kc++) {
            const int cp = pass * KCHUNKS + kc;
            CP_WAIT(1);
            __syncthreads();

            const int cp2 = cp + 2;
            if (cp2 < NPASS * KCHUNKS) {
                const int p2 = cp2 >> 4, k2 = cp2 & 15;
                const uint32_t bst = sb + OFF_B(cp2 % 3);
                #pragma unroll
                for (int r = 0; r < 4; r++) {
                    int row = browB + r * 32;
                    cp16(bst + (row * ROWH + bsegB) * 2,
                         g_U_h + (size_t)(p2 * BNP + row) * DIM + k2 * BKH + bsegB);
                }
            }
            CP_COMMIT();

            const uint32_t aba = sb + OFF_A(kc) + ((wm * 32 + a_row) * ROWH + a_col) * 2;
            const uint32_t bba = sb + OFF_B(cp % 3) + ((wn * 32 + b_row) * ROWH + b_col) * 2;
            #pragma unroll
            for (int ks = 0; ks < 4; ks++) {
                const int kb = ks * 16;
                uint32_t af[2][4], bq[2][4];
                #pragma unroll
                for (int p = 0; p < 2; p++)
                    ldm_x4(bq[p], bba + (p * 16 * ROWH + kb) * 2);
                #pragma unroll
                for (int i = 0; i < 2; i++)
                    ldm_x4(af[i], aba + (i * 16 * ROWH + kb) * 2);
                #pragma unroll
                for (int i = 0; i < 2; i++)
                    #pragma unroll
                    for (int j = 0; j < 4; j++)
                        mma_f16(acc[i][j], af[i], &bq[j >> 1][(j & 1) * 2]);
            }
        }
        // pass epilogue
        #pragma unroll
        for (int i = 0; i < 2; i++) {
            float slo = 0.f, shi = 0.f;
            #pragma unroll
            for (int j = 0; j < 4; j++) {
                const int c = pass * BNP + wn * 32 + j * 8 + gc * 2;
                const float v0 = v_sh[c], v1 = v_sh[c + 1];
                const float q0 = q_sh[c], q1 = q_sh[c + 1];
                float x0 = q0 + acc[i][j][0], x1 = q1 + acc[i][j][1];
                float x2 = q0 + acc[i][j][2], x3 = q1 + acc[i][j][3];
                slo += v0 * (1.f - 2.f / (__expf(2.f * x0) + 1.f))
                     + v1 * (1.f - 2.f / (__expf(2.f * x1) + 1.f));
                shi += v0 * (1.f - 2.f / (__expf(2.f * x2) + 1.f))
                     + v1 * (1.f - 2.f / (__expf(2.f * x3) + 1.f));
                #pragma unroll
                for (int r = 0; r < 4; r++) acc[i][j][r] = 0.f;
            }
            slo += __shfl_xor_sync(0xffffffffu, slo, 1);
            slo += __shfl_xor_sync(0xffffffffu, slo, 2);
            shi += __shfl_xor_sync(0xffffffffu, shi, 1);
            shi += __shfl_xor_sync(0xffffffffu, shi, 2);
            if (gc == 0) {
                atomicAdd(&score_sm[wm * 32 + i * 16 + gr], slo);
                atomicAdd(&score_sm[wm * 32 + i * 16 + gr + 8], shi);
            }
        }
    }

    __syncthreads();
    if (tid < BM)
        g_scores[(size_t)b * SEQ + l0 + tid] = score_sm[tid];
}

// ---------------------------------------------------------------------------
// Kernel 3: softmax over L per batch; zero-inits the context region of out.
// ---------------------------------------------------------------------------
__global__ void softmax_kernel(float* __restrict__ out) {
    __shared__ float sm[SEQ];
    __shared__ float red[256];
    const int b = blockIdx.x, tid = threadIdx.x;

    for (int d = tid; d < DIM; d += 256) out[b * DIM + d] = 0.f;

    float m = -1e30f;
    for (int l = tid; l < SEQ; l += 256) {
        float s = g_scores[b * SEQ + l];
        sm[l] = s;
        m = fmaxf(m, s);
    }
    red[tid] = m;
    __syncthreads();
    for (int o = 128; o; o >>= 1) {
        if (tid < o) red[tid] = fmaxf(red[tid], red[tid + o]);
        __syncthreads();
    }
    m = red[0];
    __syncthreads();

    float sum = 0.f;
    for (int l = tid; l < SEQ; l += 256) {
        float e = __expf(sm[l] - m);
        sm[l] = e;
        sum += e;
    }
    red[tid] = sum;
    __syncthreads();
    for (int o = 128; o; o >>= 1) {
        if (tid < o) red[tid] += red[tid + o];
        __syncthreads();
    }
    const float inv = 1.f / red[0];

    float* attn = out + BATCH * DIM;
    for (int l = tid; l < SEQ; l += 256) attn[b * SEQ + l] = sm[l] * inv;
}

// ---------------------------------------------------------------------------
// Kernel 4: context[b,d] += sum_{l in chunk} attn[b,l] * enc_h[b,l,d]
// fp16 enc (written by score), fp32 accumulate + atomicAdd.
// Grid (BATCH, 32): 64 rows/block.
// ---------------------------------------------------------------------------
__global__ void context_kernel(float* __restrict__ out) {
    __shared__ float attn_sm[64];
    const int b = blockIdx.x, ch = blockIdx.y, tid = threadIdx.x;
    const int lbase = ch * 64;
    if (tid < 64) attn_sm[tid] = out[BATCH * DIM + (size_t)b * SEQ + lbase + tid];
    __syncthreads();

    float acc0 = 0.f, acc1 = 0.f, acc2 = 0.f, acc3 = 0.f;
    const __half* ep = g_enc_h + ((size_t)b * SEQ + lbase) * DIM + tid * 4;
    #pragma unroll 8
    for (int l = 0; l < 64; ++l) {
        float a = attn_sm[l];
        uint2 raw = *(const uint2*)(ep + (size_t)l * DIM);
        __half2 h0 = *(__half2*)&raw.x, h1 = *(__half2*)&raw.y;
        float2 f0 = __half22float2(h0), f1 = __half22float2(h1);
        acc0 += a * f0.x; acc1 += a * f0.y;
        acc2 += a * f1.x; acc3 += a * f1.y;
    }
    float* dst = out + b * DIM + tid * 4;
    atomicAdd(dst + 0, acc0);
    atomicAdd(dst + 1, acc1);
    atomicAdd(dst + 2, acc2);
    atomicAdd(dst + 3, acc3);
}

// ---------------------------------------------------------------------------
extern "C" void kernel_launch(void* const* d_in, const int* in_sizes, int n_in,
                              void* d_out, int out_size) {
    const float* dh  = (const float*)d_in[0];   // [32,1,1024]
    const float* enc = (const float*)d_in[1];   // [32,2048,1024]
    const float* Ww  = (const float*)d_in[2];   // [1024,1024]
    const float* Wb  = (const float*)d_in[3];   // [1024]
    const float* Uw  = (const float*)d_in[4];   // [1024,1024]
    const float* Ub  = (const float*)d_in[5];   // [1024]
    const float* vw  = (const float*)d_in[6];   // [1,1024]
    float* out = (float*)d_out;                 // [32768 context | 65536 attn]

    (void)in_sizes; (void)n_in; (void)out_size;

    static bool attr_set = false;
    if (!attr_set) {
        cudaFuncSetAttribute(score_kernel,
                             cudaFuncAttributeMaxDynamicSharedMemorySize, SMEM_BYTES);
        attr_set = true;
    }

    prep_kernel<<<NUCONV_BLOCKS + NQP_BLOCKS, 256>>>(Uw, dh, Ww, Wb, Ub);

    dim3 sgrid(SEQ / BM, BATCH);   // (32, 32) = 1024 blocks
    score_kernel<<<sgrid, 256, SMEM_BYTES>>>(enc, vw);

    softmax_kernel<<<BATCH, 256>>>(out);

    dim3 cgrid(BATCH, 32);
    context_kernel<<<cgrid, 256>>>(out);
}

// round 15
// speedup vs baseline: 1.0016x; 1.0016x over previous
#include <cuda_runtime.h>
#include <cuda_fp16.h>
#include <math.h>
#include <stdint.h>

#define BATCH 32
#define SEQ   2048
#define DIM   1024

#define BM 64                       // l-rows per block
#define BNP 128                     // n per pass
#define NPASS 8                     // 8 passes cover D=1024
#define BKH 64                      // k halfs per chunk (128 B)
#define KCHUNKS 16                  // full K resident
#define ROWH 72                     // halfs per smem row (LDSM conflict-free)

#define A_CHUNK (BM * ROWH * 2)     // 9216 B
#define B_STAGE (BNP * ROWH * 2)    // 18432 B
#define OFF_A(kc) ((kc) * A_CHUNK)                       // 16 x 9216 = 147456
#define OFF_B(s)  (KCHUNKS * A_CHUNK + (s) * B_STAGE)    // +3 x 18432
#define OFF_Q     (KCHUNKS * A_CHUNK + 3 * B_STAGE)      // 202752
#define OFF_V     (OFF_Q + DIM * 4)
#define OFF_SC    (OFF_V + DIM * 4)
#define SMEM_BYTES (OFF_SC + BM * 4)                     // 211200 B

// Scratch (static __device__ — no allocation inside kernel_launch)
__device__ float  g_q[BATCH * DIM];
__device__ float  g_scores[BATCH * SEQ];
__device__ __half g_enc_h[(size_t)BATCH * SEQ * DIM];   // written by score pass 0
__device__ __half g_U_h[DIM * DIM];                     // fp16 copy of Uw (prep)

__device__ __forceinline__ uint32_t smem_u32(const void* p) {
    uint32_t a;
    asm("{ .reg .u64 t; cvta.to.shared.u64 t, %1; cvt.u32.u64 %0, t; }"
        : "=r"(a) : "l"(p));
    return a;
}

__device__ __forceinline__ void cp16(uint32_t dst, const void* src) {
    asm volatile("cp.async.cg.shared.global [%0], [%1], 16;"
                 :: "r"(dst), "l"(src) : "memory");
}
#define CP_COMMIT() asm volatile("cp.async.commit_group;" ::: "memory")
#define CP_WAIT(n)  asm volatile("cp.async.wait_group %0;" :: "n"(n) : "memory")

__device__ __forceinline__ void ldm_x4(uint32_t r[4], uint32_t addr) {
    asm volatile("ldmatrix.sync.aligned.m8n8.x4.shared.b16 {%0,%1,%2,%3}, [%4];"
                 : "=r"(r[0]), "=r"(r[1]), "=r"(r[2]), "=r"(r[3]) : "r"(addr));
}

__device__ __forceinline__ void mma_f16(float c[4], const uint32_t a[4], const uint32_t b[2]) {
    asm volatile(
        "mma.sync.aligned.m16n8k16.row.col.f32.f16.f16.f32 "
        "{%0,%1,%2,%3}, {%4,%5,%6,%7}, {%8,%9}, {%0,%1,%2,%3};"
        : "+f"(c[0]), "+f"(c[1]), "+f"(c[2]), "+f"(c[3])
        : "r"(a[0]), "r"(a[1]), "r"(a[2]), "r"(a[3]), "r"(b[0]), "r"(b[1]));
}

// ---------------------------------------------------------------------------
// Kernel 0 (tiny prep): U fp32->fp16 + q' projection.
// ---------------------------------------------------------------------------
#define NU8 ((size_t)DIM * DIM / 8)                    // 131072
#define NUCONV_BLOCKS ((unsigned)((NU8 + 255) / 256))  // 512
#define NQP_BLOCKS    (BATCH * DIM / 8)                // 4096

__global__ void prep_kernel(const float* __restrict__ Uw,
                            const float* __restrict__ dh,
                            const float* __restrict__ Ww,
                            const float* __restrict__ Wb,
                            const float* __restrict__ Ub) {
    if (blockIdx.x < NUCONV_BLOCKS) {
        size_t k = (size_t)blockIdx.x * 256 + threadIdx.x;
        if (k >= NU8) return;
        const float4* src = (const float4*)Uw;
        float4 f0 = src[k * 2], f1 = src[k * 2 + 1];
        __half2 h[4];
        h[0] = __floats2half2_rn(f0.x, f0.y);
        h[1] = __floats2half2_rn(f0.z, f0.w);
        h[2] = __floats2half2_rn(f1.x, f1.y);
        h[3] = __floats2half2_rn(f1.z, f1.w);
        ((uint4*)g_U_h)[k] = *(uint4*)h;
        return;
    }
    int qgid = (int)(blockIdx.x - NUCONV_BLOCKS) * 256 + threadIdx.x;
    int warp = qgid >> 5;
    int lane = threadIdx.x & 31;
    if (warp >= BATCH * DIM) return;
    int b = warp / DIM, d = warp % DIM;
    const float* x = dh + b * DIM;
    const float* w = Ww + (size_t)d * DIM;
    float s = 0.f;
    #pragma unroll 4
    for (int e = lane; e < DIM; e += 32) s += x[e] * w[e];
    #pragma unroll
    for (int o = 16; o; o >>= 1) s += __shfl_xor_sync(0xffffffffu, s, o);
    if (lane == 0) g_q[warp] = s + Wb[d] + Ub[d];
}

// ---------------------------------------------------------------------------
// Kernel 2 (dominant): one block owns a full (b, 64-l-row) tile across ALL of
// D. A (enc fp32) is read ONCE, converted in-kernel to a resident full-K fp16
// smem tile (pass 0), and STG'd to g_enc_h for the context kernel (free:
// DRAM idle during compute). B (U fp16) streams L2->smem, 3-stage cp.async.
// 8 n-passes of 128; per-pass fused tanh*v epilogue into smem score partials
// (no global atomics). Grid (32, 32) = 1024 blocks, 256 threads, 1 CTA/SM.
// Warps: 2m x 4n, warp tile 32x32.
// ---------------------------------------------------------------------------
__global__ __launch_bounds__(256, 1)
void score_kernel(const float* __restrict__ enc,
                  const float* __restrict__ vw) {
    extern __shared__ char smc[];
    const uint32_t sb = smem_u32(smc);

    const int tid  = threadIdx.x;
    const int wid  = tid >> 5;
    const int lane = tid & 31;
    const int wm   = wid >> 2;         // 0..1 -> m offset wm*32
    const int wn   = wid & 3;          // 0..3 -> n offset wn*32
    const int gr   = lane >> 2;
    const int gc   = lane & 3;

    const int l0 = blockIdx.x * BM;
    const int b  = blockIdx.y;

    float* q_sh = (float*)(smc + OFF_Q);
    float* v_sh = (float*)(smc + OFF_V);
    float* score_sm = (float*)(smc + OFF_SC);
    for (int i = tid; i < DIM; i += 256) {
        q_sh[i] = g_q[b * DIM + i];
        v_sh[i] = vw[i];
    }
    if (tid < BM) score_sm[tid] = 0.f;

    // A conversion mapping: 4 threads/row, 16 floats each
    const int crowA = tid >> 2;          // 0..63
    const int csegA = (tid & 3) * 16;
    const float* Aenc = enc + ((size_t)(b * SEQ + l0 + crowA)) * DIM + csegA;
    __half* EncOut = g_enc_h + ((size_t)(b * SEQ + l0 + crowA)) * DIM + csegA;
    const uint32_t aStsOff = (crowA * ROWH + csegA) * 2;

    // B cp.async mapping: 32 rows/pass x 8 segs, 4 passes
    const int browB = tid >> 3;          // 0..31
    const int bsegB = (tid & 7) * 8;

    uint32_t a16[8];
    float4 vld[4];

    // ---- prologue ----
    // A chunk 0: LDG -> cvt -> STS A16[0] + STG enc_h
    #pragma unroll
    for (int j = 0; j < 4; j++) vld[j] = *(const float4*)(Aenc + j * 4);
    #pragma unroll
    for (int j = 0; j < 4; j++) {
        __half2 h0 = __floats2half2_rn(vld[j].x, vld[j].y);
        __half2 h1 = __floats2half2_rn(vld[j].z, vld[j].w);
        a16[j * 2] = *(uint32_t*)&h0; a16[j * 2 + 1] = *(uint32_t*)&h1;
    }
    {
        uint4* d = (uint4*)(smc + OFF_A(0) + aStsOff);
        d[0] = *(uint4*)&a16[0]; d[1] = *(uint4*)&a16[4];
        ((uint4*)EncOut)[0] = *(uint4*)&a16[0];
        ((uint4*)EncOut)[1] = *(uint4*)&a16[4];
    }
    // A chunk 1: LDG -> cvt -> hold (STS at iter 0) + STG
    #pragma unroll
    for (int j = 0; j < 4; j++) vld[j] = *(const float4*)(Aenc + BKH + j * 4);
    #pragma unroll
    for (int j = 0; j < 4; j++) {
        __half2 h0 = __floats2half2_rn(vld[j].x, vld[j].y);
        __half2 h1 = __floats2half2_rn(vld[j].z, vld[j].w);
        a16[j * 2] = *(uint32_t*)&h0; a16[j * 2 + 1] = *(uint32_t*)&h1;
    }
    ((uint4*)(EncOut + BKH))[0] = *(uint4*)&a16[0];
    ((uint4*)(EncOut + BKH))[1] = *(uint4*)&a16[4];

    // B chunks cp=0,1 (pass 0, k=0,1)
    #pragma unroll
    for (int g = 0; g < 2; g++) {
        const uint32_t bst = sb + OFF_B(g);
        #pragma unroll
        for (int r = 0; r < 4; r++) {
            int row = browB + r * 32;
            cp16(bst + (row * ROWH + bsegB) * 2,
                 g_U_h + (size_t)row * DIM + g * BKH + bsegB);
        }
        CP_COMMIT();
    }

    // ldmatrix lane address components
    const int a_row = (lane & 7) + ((lane >> 3) & 1) * 8;
    const int a_col = ((lane >> 4) & 1) * 8;
    const int b_row = (lane & 7) + ((lane >> 4) & 1) * 8;
    const int b_col = ((lane >> 3) & 1) * 8;

    float acc[2][4][4];
    #pragma unroll
    for (int i = 0; i < 2; i++)
        #pragma unroll
        for (int j = 0; j < 4; j++)
            #pragma unroll
            for (int r = 0; r < 4; r++) acc[i][j][r] = 0.f;

    // ================= pass 0 (with A conversion) =================
    for (int kc = 0; kc < KCHUNKS; kc++) {
        CP_WAIT(1);
        __syncthreads();

        // STS pending fp16 chunk kc+1 into resident slot
        if (kc + 1 < KCHUNKS) {
            uint4* d = (uint4*)(smc + OFF_A(kc + 1) + aStsOff);
            d[0] = *(uint4*)&a16[0]; d[1] = *(uint4*)&a16[4];
        }
        // LDG A chunk kc+2 (converted after the mma below)
        const int kn = kc + 2;
        if (kn < KCHUNKS) {
            const float* src = Aenc + kn * BKH;
            #pragma unroll
            for (int j = 0; j < 4; j++) vld[j] = *(const float4*)(src + j * 4);
        }
        // B prefetch for global chunk cp2 = kc+2 (maps into pass 1 at the end)
        {
            const int cp2 = kc + 2;
            const int p2 = cp2 >> 4, k2 = cp2 & 15;
            const uint32_t bst = sb + OFF_B(cp2 % 3);
            #pragma unroll
            for (int r = 0; r < 4; r++) {
                int row = browB + r * 32;
                cp16(bst + (row * ROWH + bsegB) * 2,
                     g_U_h + (size_t)(p2 * BNP + row) * DIM + k2 * BKH + bsegB);
            }
        }
        CP_COMMIT();

        // mma on chunk kc: A16[kc] resident, B stage kc%3
        const uint32_t aba = sb + OFF_A(kc) + ((wm * 32 + a_row) * ROWH + a_col) * 2;
        const uint32_t bba = sb + OFF_B(kc % 3) + ((wn * 32 + b_row) * ROWH + b_col) * 2;
        #pragma unroll
        for (int ks = 0; ks < 4; ks++) {
            const int kb = ks * 16;
            uint32_t af[2][4], bq[2][4];
            #pragma unroll
            for (int p = 0; p < 2; p++)
                ldm_x4(bq[p], bba + (p * 16 * ROWH + kb) * 2);
            #pragma unroll
            for (int i = 0; i < 2; i++)
                ldm_x4(af[i], aba + (i * 16 * ROWH + kb) * 2);
            #pragma unroll
            for (int i = 0; i < 2; i++)
                #pragma unroll
                for (int j = 0; j < 4; j++)
                    mma_f16(acc[i][j], af[i], &bq[j >> 1][(j & 1) * 2]);
        }

        // convert chunk kc+2 (LDG latency drained by the mma block) + STG
        if (kn < KCHUNKS) {
            #pragma unroll
            for (int j = 0; j < 4; j++) {
                __half2 h0 = __floats2half2_rn(vld[j].x, vld[j].y);
                __half2 h1 = __floats2half2_rn(vld[j].z, vld[j].w);
                a16[j * 2] = *(uint32_t*)&h0; a16[j * 2 + 1] = *(uint32_t*)&h1;
            }
            ((uint4*)(EncOut + kn * BKH))[0] = *(uint4*)&a16[0];
            ((uint4*)(EncOut + kn * BKH))[1] = *(uint4*)&a16[4];
        }
    }
    // pass 0 epilogue
    #pragma unroll
    for (int i = 0; i < 2; i++) {
        float slo = 0.f, shi = 0.f;
        #pragma unroll
        for (int j = 0; j < 4; j++) {
            const int c = wn * 32 + j * 8 + gc * 2;   // pass 0: global n = c
            const float v0 = v_sh[c], v1 = v_sh[c + 1];
            const float q0 = q_sh[c], q1 = q_sh[c + 1];
            float x0 = q0 + acc[i][j][0], x1 = q1 + acc[i][j][1];
            float x2 = q0 + acc[i][j][2], x3 = q1 + acc[i][j][3];
            slo += v0 * (1.f - 2.f / (__expf(2.f * x0) + 1.f))
                 + v1 * (1.f - 2.f / (__expf(2.f * x1) + 1.f));
            shi += v0 * (1.f - 2.f / (__expf(2.f * x2) + 1.f))
                 + v1 * (1.f - 2.f / (__expf(2.f * x3) + 1.f));
            #pragma unroll
            for (int r = 0; r < 4; r++) acc[i][j][r] = 0.f;
        }
        slo += __shfl_xor_sync(0xffffffffu, slo, 1);
        slo += __shfl_xor_sync(0xffffffffu, slo, 2);
        shi += __shfl_xor_sync(0xffffffffu, shi, 1);
        shi += __shfl_xor_sync(0xffffffffu, shi, 2);
        if (gc == 0) {
            atomicAdd(&score_sm[wm * 32 + i * 16 + gr], slo);
            atomicAdd(&score_sm[wm * 32 + i * 16 + gr + 8], shi);
        }
    }

    // ================= passes 1..7 (A resident, lean loop) =================
    for (int pass = 1; pass < NPASS; pass++) {
        for (int kc = 0; kc < KCHUNKS; kc++) {
            const int cp = pass * KCHUNKS + kc;
            CP_WAIT(1);
            __syncthreads();

            const int cp2 = cp + 2;
            if (cp2 < NPASS * KCHUNKS) {
                const int p2 = cp2 >> 4, k2 = cp2 & 15;
                const uint32_t bst = sb + OFF_B(cp2 % 3);
                #pragma unroll
                for (int r = 0; r < 4; r++) {
                    int row = browB + r * 32;
                    cp16(bst + (row * ROWH + bsegB) * 2,
                         g_U_h + (size_t)(p2 * BNP + row) * DIM + k2 * BKH + bsegB);
                }
            }
            CP_COMMIT();

            const uint32_t aba = sb + OFF_A(kc) + ((wm * 32 + a_row) * ROWH + a_col) * 2;
            const uint32_t bba = sb + OFF_B(cp % 3) + ((wn * 32 + b_row) * ROWH + b_col) * 2;
            #pragma unroll
            for (int ks = 0; ks < 4; ks++) {
                const int kb = ks * 16;
                uint32_t af[2][4], bq[2][4];
                #pragma unroll
                for (int p = 0; p < 2; p++)
                    ldm_x4(bq[p], bba + (p * 16 * ROWH + kb) * 2);
                #pragma unroll
                for (int i = 0; i < 2; i++)
                    ldm_x4(af[i], aba + (i * 16 * ROWH + kb) * 2);
                #pragma unroll
                for (int i = 0; i < 2; i++)
                    #pragma unroll
                    for (int j = 0; j < 4; j++)
                        mma_f16(acc[i][j], af[i], &bq[j >> 1][(j & 1) * 2]);
            }
        }
        // pass epilogue
        #pragma unroll
        for (int i = 0; i < 2; i++) {
            float slo = 0.f, shi = 0.f;
            #pragma unroll
            for (int j = 0; j < 4; j++) {
                const int c = pass * BNP + wn * 32 + j * 8 + gc * 2;
                const float v0 = v_sh[c], v1 = v_sh[c + 1];
                const float q0 = q_sh[c], q1 = q_sh[c + 1];
                float x0 = q0 + acc[i][j][0], x1 = q1 + acc[i][j][1];
                float x2 = q0 + acc[i][j][2], x3 = q1 + acc[i][j][3];
                slo += v0 * (1.f - 2.f / (__expf(2.f * x0) + 1.f))
                     + v1 * (1.f - 2.f / (__expf(2.f * x1) + 1.f));
                shi += v0 * (1.f - 2.f / (__expf(2.f * x2) + 1.f))
                     + v1 * (1.f - 2.f / (__expf(2.f * x3) + 1.f));
                #pragma unroll
                for (int r = 0; r < 4; r++) acc[i][j][r] = 0.f;
            }
            slo += __shfl_xor_sync(0xffffffffu, slo, 1);
            slo += __shfl_xor_sync(0xffffffffu, slo, 2);
            shi += __shfl_xor_sync(0xffffffffu, shi, 1);
            shi += __shfl_xor_sync(0xffffffffu, shi, 2);
            if (gc == 0) {
                atomicAdd(&score_sm[wm * 32 + i * 16 + gr], slo);
                atomicAdd(&score_sm[wm * 32 + i * 16 + gr + 8], shi);
            }
        }
    }

    __syncthreads();
    if (tid < BM)
        g_scores[(size_t)b * SEQ + l0 + tid] = score_sm[tid];
}

// ---------------------------------------------------------------------------
// Kernel 3: softmax over L per batch; zero-inits the context region of out.
// ---------------------------------------------------------------------------
__global__ void softmax_kernel(float* __restrict__ out) {
    __shared__ float sm[SEQ];
    __shared__ float red[256];
    const int b = blockIdx.x, tid = threadIdx.x;

    for (int d = tid; d < DIM; d += 256) out[b * DIM + d] = 0.f;

    float m = -1e30f;
    for (int l = tid; l < SEQ; l += 256) {
        float s = g_scores[b * SEQ + l];
        sm[l] = s;
        m = fmaxf(m, s);
    }
    red[tid] = m;
    __syncthreads();
    for (int o = 128; o; o >>= 1) {
        if (tid < o) red[tid] = fmaxf(red[tid], red[tid + o]);
        __syncthreads();
    }
    m = red[0];
    __syncthreads();

    float sum = 0.f;
    for (int l = tid; l < SEQ; l += 256) {
        float e = __expf(sm[l] - m);
        sm[l] = e;
        sum += e;
    }
    red[tid] = sum;
    __syncthreads();
    for (int o = 128; o; o >>= 1) {
        if (tid < o) red[tid] += red[tid + o];
        __syncthreads();
    }
    const float inv = 1.f / red[0];

    float* attn = out + BATCH * DIM;
    for (int l = tid; l < SEQ; l += 256) attn[b * SEQ + l] = sm[l] * inv;
}

// ---------------------------------------------------------------------------
// Kernel 4: context[b,d] += sum_{l in chunk} attn[b,l] * enc_h[b,l,d]
// fp16 enc (written by score), fp32 accumulate + atomicAdd.
// Grid (BATCH, 32): 64 rows/block.
// ---------------------------------------------------------------------------
__global__ void context_kernel(float* __restrict__ out) {
    __shared__ float attn_sm[64];
    const int b = blockIdx.x, ch = blockIdx.y, tid = threadIdx.x;
    const int lbase = ch * 64;
    if (tid < 64) attn_sm[tid] = out[BATCH * DIM + (size_t)b * SEQ + lbase + tid];
    __syncthreads();

    float acc0 = 0.f, acc1 = 0.f, acc2 = 0.f, acc3 = 0.f;
    const __half* ep = g_enc_h + ((size_t)b * SEQ + lbase) * DIM + tid * 4;
    #pragma unroll 8
    for (int l = 0; l < 64; ++l) {
        float a = attn_sm[l];
        uint2 raw = *(const uint2*)(ep + (size_t)l * DIM);
        __half2 h0 = *(__half2*)&raw.x, h1 = *(__half2*)&raw.y;
        float2 f0 = __half22float2(h0), f1 = __half22float2(h1);
        acc0 += a * f0.x; acc1 += a * f0.y;
        acc2 += a * f1.x; acc3 += a * f1.y;
    }
    float* dst = out + b * DIM + tid * 4;
    atomicAdd(dst + 0, acc0);
    atomicAdd(dst + 1, acc1);
    atomicAdd(dst + 2, acc2);
    atomicAdd(dst + 3, acc3);
}

// ---------------------------------------------------------------------------
extern "C" void kernel_launch(void* const* d_in, const int* in_sizes, int n_in,
                              void* d_out, int out_size) {
    const float* dh  = (const float*)d_in[0];   // [32,1,1024]
    const float* enc = (const float*)d_in[1];   // [32,2048,1024]
    const float* Ww  = (const float*)d_in[2];   // [1024,1024]
    const float* Wb  = (const float*)d_in[3];   // [1024]
    const float* Uw  = (const float*)d_in[4];   // [1024,1024]
    const float* Ub  = (const float*)d_in[5];   // [1024]
    const float* vw  = (const float*)d_in[6];   // [1,1024]
    float* out = (float*)d_out;                 // [32768 context | 65536 attn]

    (void)in_sizes; (void)n_in; (void)out_size;

    static bool attr_set = false;
    if (!attr_set) {
        cudaFuncSetAttribute(score_kernel,
                             cudaFuncAttributeMaxDynamicSharedMemorySize, SMEM_BYTES);
        attr_set = true;
    }

    prep_kernel<<<NUCONV_BLOCKS + NQP_BLOCKS, 256>>>(Uw, dh, Ww, Wb, Ub);

    dim3 sgrid(SEQ / BM, BATCH);   // (32, 32) = 1024 blocks
    score_kernel<<<sgrid, 256, SMEM_BYTES>>>(enc, vw);

    softmax_kernel<<<BATCH, 256>>>(out);

    dim3 cgrid(BATCH, 32);
    context_kernel<<<cgrid, 256>>>(out);
}

// round 16
// speedup vs baseline: 1.0023x; 1.0007x over previous
#include <cuda_runtime.h>
#include <cuda_fp16.h>
#include <math.h>
#include <stdint.h>

#define BATCH 32
#define SEQ   2048
#define DIM   1024

#define BM 64                       // l-rows per block
#define BNP 128                     // n per pass
#define NPASS 8                     // 8 passes cover D=1024
#define BKH 64                      // k halfs per chunk (128 B)
#define KCHUNKS 16                  // full K resident
#define ROWH 72                     // halfs per smem row (LDSM conflict-free)

#define A_CHUNK (BM * ROWH * 2)     // 9216 B
#define B_STAGE (BNP * ROWH * 2)    // 18432 B
#define OFF_A(kc) ((kc) * A_CHUNK)                       // 16 x 9216 = 147456
#define OFF_B(s)  (KCHUNKS * A_CHUNK + (s) * B_STAGE)    // +3 x 18432
#define OFF_Q     (KCHUNKS * A_CHUNK + 3 * B_STAGE)      // 202752
#define OFF_V     (OFF_Q + DIM * 4)
#define OFF_SC    (OFF_V + DIM * 4)
#define SMEM_BYTES (OFF_SC + BM * 4)                     // 211200 B

// Scratch (static __device__ — no allocation inside kernel_launch)
__device__ float  g_q[BATCH * DIM];
__device__ float  g_scores[BATCH * SEQ];
__device__ __half g_enc_h[(size_t)BATCH * SEQ * DIM];   // written by score pass 0
__device__ __half g_U_h[DIM * DIM];                     // fp16 copy of Uw (prep)

__device__ __forceinline__ uint32_t smem_u32(const void* p) {
    uint32_t a;
    asm("{ .reg .u64 t; cvta.to.shared.u64 t, %1; cvt.u32.u64 %0, t; }"
        : "=r"(a) : "l"(p));
    return a;
}

__device__ __forceinline__ void cp16(uint32_t dst, const void* src) {
    asm volatile("cp.async.cg.shared.global [%0], [%1], 16;"
                 :: "r"(dst), "l"(src) : "memory");
}
#define CP_COMMIT() asm volatile("cp.async.commit_group;" ::: "memory")
#define CP_WAIT(n)  asm volatile("cp.async.wait_group %0;" :: "n"(n) : "memory")

__device__ __forceinline__ void ldm_x4(uint32_t r[4], uint32_t addr) {
    asm volatile("ldmatrix.sync.aligned.m8n8.x4.shared.b16 {%0,%1,%2,%3}, [%4];"
                 : "=r"(r[0]), "=r"(r[1]), "=r"(r[2]), "=r"(r[3]) : "r"(addr));
}

__device__ __forceinline__ void mma_f16(float c[4], const uint32_t a[4], const uint32_t b[2]) {
    asm volatile(
        "mma.sync.aligned.m16n8k16.row.col.f32.f16.f16.f32 "
        "{%0,%1,%2,%3}, {%4,%5,%6,%7}, {%8,%9}, {%0,%1,%2,%3};"
        : "+f"(c[0]), "+f"(c[1]), "+f"(c[2]), "+f"(c[3])
        : "r"(a[0]), "r"(a[1]), "r"(a[2]), "r"(a[3]), "r"(b[0]), "r"(b[1]));
}

// ---------------------------------------------------------------------------
// Kernel 0 (tiny prep): U fp32->fp16 + q' projection.
// ---------------------------------------------------------------------------
#define NU8 ((size_t)DIM * DIM / 8)                    // 131072
#define NUCONV_BLOCKS ((unsigned)((NU8 + 255) / 256))  // 512
#define NQP_BLOCKS    (BATCH * DIM / 8)                // 4096

__global__ void prep_kernel(const float* __restrict__ Uw,
                            const float* __restrict__ dh,
                            const float* __restrict__ Ww,
                            const float* __restrict__ Wb,
                            const float* __restrict__ Ub) {
    if (blockIdx.x < NUCONV_BLOCKS) {
        size_t k = (size_t)blockIdx.x * 256 + threadIdx.x;
        if (k >= NU8) return;
        const float4* src = (const float4*)Uw;
        float4 f0 = src[k * 2], f1 = src[k * 2 + 1];
        __half2 h[4];
        h[0] = __floats2half2_rn(f0.x, f0.y);
        h[1] = __floats2half2_rn(f0.z, f0.w);
        h[2] = __floats2half2_rn(f1.x, f1.y);
        h[3] = __floats2half2_rn(f1.z, f1.w);
        ((uint4*)g_U_h)[k] = *(uint4*)h;
        return;
    }
    int qgid = (int)(blockIdx.x - NUCONV_BLOCKS) * 256 + threadIdx.x;
    int warp = qgid >> 5;
    int lane = threadIdx.x & 31;
    if (warp >= BATCH * DIM) return;
    int b = warp / DIM, d = warp % DIM;
    const float* x = dh + b * DIM;
    const float* w = Ww + (size_t)d * DIM;
    float s = 0.f;
    #pragma unroll 4
    for (int e = lane; e < DIM; e += 32) s += x[e] * w[e];
    #pragma unroll
    for (int o = 16; o; o >>= 1) s += __shfl_xor_sync(0xffffffffu, s, o);
    if (lane == 0) g_q[warp] = s + Wb[d] + Ub[d];
}

// ---------------------------------------------------------------------------
// Kernel 2 (dominant): one block owns a full (b, 64-l-row) tile across ALL of
// D. A (enc fp32) is read ONCE, converted in-kernel to a resident full-K fp16
// smem tile (pass 0), and STG'd to g_enc_h for the context kernel (free:
// DRAM idle during compute). B (U fp16) streams L2->smem, 3-stage cp.async.
// 8 n-passes of 128; per-pass fused tanh*v epilogue into smem score partials
// (no global atomics). Grid (32, 32) = 1024 blocks, 256 threads, 1 CTA/SM.
// Warps: 2m x 4n, warp tile 32x32.
// ---------------------------------------------------------------------------
__global__ __launch_bounds__(256, 1)
void score_kernel(const float* __restrict__ enc,
                  const float* __restrict__ vw) {
    extern __shared__ char smc[];
    const uint32_t sb = smem_u32(smc);

    const int tid  = threadIdx.x;
    const int wid  = tid >> 5;
    const int lane = tid & 31;
    const int wm   = wid >> 2;         // 0..1 -> m offset wm*32
    const int wn   = wid & 3;          // 0..3 -> n offset wn*32
    const int gr   = lane >> 2;
    const int gc   = lane & 3;

    const int l0 = blockIdx.x * BM;
    const int b  = blockIdx.y;

    float* q_sh = (float*)(smc + OFF_Q);
    float* v_sh = (float*)(smc + OFF_V);
    float* score_sm = (float*)(smc + OFF_SC);
    for (int i = tid; i < DIM; i += 256) {
        q_sh[i] = g_q[b * DIM + i];
        v_sh[i] = vw[i];
    }
    if (tid < BM) score_sm[tid] = 0.f;

    // A conversion mapping: 4 threads/row, 16 floats each
    const int crowA = tid >> 2;          // 0..63
    const int csegA = (tid & 3) * 16;
    const float* Aenc = enc + ((size_t)(b * SEQ + l0 + crowA)) * DIM + csegA;
    __half* EncOut = g_enc_h + ((size_t)(b * SEQ + l0 + crowA)) * DIM + csegA;
    const uint32_t aStsOff = (crowA * ROWH + csegA) * 2;

    // B cp.async mapping: 32 rows/pass x 8 segs, 4 passes
    const int browB = tid >> 3;          // 0..31
    const int bsegB = (tid & 7) * 8;

    uint32_t a16[8];
    float4 vld[4];

    // ---- prologue ----
    // A chunk 0: LDG -> cvt -> STS A16[0] + STG enc_h
    #pragma unroll
    for (int j = 0; j < 4; j++) vld[j] = *(const float4*)(Aenc + j * 4);
    #pragma unroll
    for (int j = 0; j < 4; j++) {
        __half2 h0 = __floats2half2_rn(vld[j].x, vld[j].y);
        __half2 h1 = __floats2half2_rn(vld[j].z, vld[j].w);
        a16[j * 2] = *(uint32_t*)&h0; a16[j * 2 + 1] = *(uint32_t*)&h1;
    }
    {
        uint4* d = (uint4*)(smc + OFF_A(0) + aStsOff);
        d[0] = *(uint4*)&a16[0]; d[1] = *(uint4*)&a16[4];
        ((uint4*)EncOut)[0] = *(uint4*)&a16[0];
        ((uint4*)EncOut)[1] = *(uint4*)&a16[4];
    }
    // A chunk 1: LDG -> cvt -> hold (STS at iter 0) + STG
    #pragma unroll
    for (int j = 0; j < 4; j++) vld[j] = *(const float4*)(Aenc + BKH + j * 4);
    #pragma unroll
    for (int j = 0; j < 4; j++) {
        __half2 h0 = __floats2half2_rn(vld[j].x, vld[j].y);
        __half2 h1 = __floats2half2_rn(vld[j].z, vld[j].w);
        a16[j * 2] = *(uint32_t*)&h0; a16[j * 2 + 1] = *(uint32_t*)&h1;
    }
    ((uint4*)(EncOut + BKH))[0] = *(uint4*)&a16[0];
    ((uint4*)(EncOut + BKH))[1] = *(uint4*)&a16[4];

    // B chunks cp=0,1 (pass 0, k=0,1)
    #pragma unroll
    for (int g = 0; g < 2; g++) {
        const uint32_t bst = sb + OFF_B(g);
        #pragma unroll
        for (int r = 0; r < 4; r++) {
            int row = browB + r * 32;
            cp16(bst + (row * ROWH + bsegB) * 2,
                 g_U_h + (size_t)row * DIM + g * BKH + bsegB);
        }
        CP_COMMIT();
    }

    // ldmatrix lane address components
    const int a_row = (lane & 7) + ((lane >> 3) & 1) * 8;
    const int a_col = ((lane >> 4) & 1) * 8;
    const int b_row = (lane & 7) + ((lane >> 4) & 1) * 8;
    const int b_col = ((lane >> 3) & 1) * 8;

    float acc[2][4][4];
    #pragma unroll
    for (int i = 0; i < 2; i++)
        #pragma unroll
        for (int j = 0; j < 4; j++)
            #pragma unroll
            for (int r = 0; r < 4; r++) acc[i][j][r] = 0.f;

    // ================= pass 0 (with A conversion) =================
    for (int kc = 0; kc < KCHUNKS; kc++) {
        CP_WAIT(1);
        __syncthreads();

        // STS pending fp16 chunk kc+1 into resident slot
        if (kc + 1 < KCHUNKS) {
            uint4* d = (uint4*)(smc + OFF_A(kc + 1) + aStsOff);
            d[0] = *(uint4*)&a16[0]; d[1] = *(uint4*)&a16[4];
        }
        // LDG A chunk kc+2 (converted after the mma below)
        const int kn = kc + 2;
        if (kn < KCHUNKS) {
            const float* src = Aenc + kn * BKH;
            #pragma unroll
            for (int j = 0; j < 4; j++) vld[j] = *(const float4*)(src + j * 4);
        }
        // B prefetch for global chunk cp2 = kc+2 (maps into pass 1 at the end)
        {
            const int cp2 = kc + 2;
            const int p2 = cp2 >> 4, k2 = cp2 & 15;
            const uint32_t bst = sb + OFF_B(cp2 % 3);
            #pragma unroll
            for (int r = 0; r < 4; r++) {
                int row = browB + r * 32;
                cp16(bst + (row * ROWH + bsegB) * 2,
                     g_U_h + (size_t)(p2 * BNP + row) * DIM + k2 * BKH + bsegB);
            }
        }
        CP_COMMIT();

        // mma on chunk kc: A16[kc] resident, B stage kc%3
        const uint32_t aba = sb + OFF_A(kc) + ((wm * 32 + a_row) * ROWH + a_col) * 2;
        const uint32_t bba = sb + OFF_B(kc % 3) + ((wn * 32 + b_row) * ROWH + b_col) * 2;
        #pragma unroll
        for (int ks = 0; ks < 4; ks++) {
            const int kb = ks * 16;
            uint32_t af[2][4], bq[2][4];
            #pragma unroll
            for (int p = 0; p < 2; p++)
                ldm_x4(bq[p], bba + (p * 16 * ROWH + kb) * 2);
            #pragma unroll
            for (int i = 0; i < 2; i++)
                ldm_x4(af[i], aba + (i * 16 * ROWH + kb) * 2);
            #pragma unroll
            for (int i = 0; i < 2; i++)
                #pragma unroll
                for (int j = 0; j < 4; j++)
                    mma_f16(acc[i][j], af[i], &bq[j >> 1][(j & 1) * 2]);
        }

        // convert chunk kc+2 (LDG latency drained by the mma block) + STG
        if (kn < KCHUNKS) {
            #pragma unroll
            for (int j = 0; j < 4; j++) {
                __half2 h0 = __floats2half2_rn(vld[j].x, vld[j].y);
                __half2 h1 = __floats2half2_rn(vld[j].z, vld[j].w);
                a16[j * 2] = *(uint32_t*)&h0; a16[j * 2 + 1] = *(uint32_t*)&h1;
            }
            ((uint4*)(EncOut + kn * BKH))[0] = *(uint4*)&a16[0];
            ((uint4*)(EncOut + kn * BKH))[1] = *(uint4*)&a16[4];
        }
    }
    // pass 0 epilogue
    #pragma unroll
    for (int i = 0; i < 2; i++) {
        float slo = 0.f, shi = 0.f;
        #pragma unroll
        for (int j = 0; j < 4; j++) {
            const int c = wn * 32 + j * 8 + gc * 2;   // pass 0: global n = c
            const float v0 = v_sh[c], v1 = v_sh[c + 1];
            const float q0 = q_sh[c], q1 = q_sh[c + 1];
            float x0 = q0 + acc[i][j][0], x1 = q1 + acc[i][j][1];
            float x2 = q0 + acc[i][j][2], x3 = q1 + acc[i][j][3];
            slo += v0 * (1.f - 2.f / (__expf(2.f * x0) + 1.f))
                 + v1 * (1.f - 2.f / (__expf(2.f * x1) + 1.f));
            shi += v0 * (1.f - 2.f / (__expf(2.f * x2) + 1.f))
                 + v1 * (1.f - 2.f / (__expf(2.f * x3) + 1.f));
            #pragma unroll
            for (int r = 0; r < 4; r++) acc[i][j][r] = 0.f;
        }
        slo += __shfl_xor_sync(0xffffffffu, slo, 1);
        slo += __shfl_xor_sync(0xffffffffu, slo, 2);
        shi += __shfl_xor_sync(0xffffffffu, shi, 1);
        shi += __shfl_xor_sync(0xffffffffu, shi, 2);
        if (gc == 0) {
            atomicAdd(&score_sm[wm * 32 + i * 16 + gr], slo);
            atomicAdd(&score_sm[wm * 32 + i * 16 + gr + 8], shi);
        }
    }

    // ================= passes 1..7 (A resident, lean loop) =================
    for (int pass = 1; pass < NPASS; pass++) {
        for (int kc = 0; kc < KCHUNKS; kc++) {
            const int cp = pass * KCHUNKS + kc;
            CP_WAIT(1);
            __syncthreads();

            const int cp2 = cp + 2;
            if (cp2 < NPASS * KCHUNKS) {
                const int p2 = cp2 >> 4, k2 = cp2 & 15;
                const uint32_t bst = sb + OFF_B(cp2 % 3);
                #pragma unroll
                for (int r = 0; r < 4; r++) {
                    int row = browB + r * 32;
                    cp16(bst + (row * ROWH + bsegB) * 2,
                         g_U_h + (size_t)(p2 * BNP + row) * DIM + k2 * BKH + bsegB);
                }
            }
            CP_COMMIT();

            const uint32_t aba = sb + OFF_A(kc) + ((wm * 32 + a_row) * ROWH + a_col) * 2;
            const uint32_t bba = sb + OFF_B(cp % 3) + ((wn * 32 + b_row) * ROWH + b_col) * 2;
            #pragma unroll
            for (int ks = 0; ks < 4; ks++) {
                const int kb = ks * 16;
                uint32_t af[2][4], bq[2][4];
                #pragma unroll
                for (int p = 0; p < 2; p++)
                    ldm_x4(bq[p], bba + (p * 16 * ROWH + kb) * 2);
                #pragma unroll
                for (int i = 0; i < 2; i++)
                    ldm_x4(af[i], aba + (i * 16 * ROWH + kb) * 2);
                #pragma unroll
                for (int i = 0; i < 2; i++)
                    #pragma unroll
                    for (int j = 0; j < 4; j++)
                        mma_f16(acc[i][j], af[i], &bq[j >> 1][(j & 1) * 2]);
            }
        }
        // pass epilogue
        #pragma unroll
        for (int i = 0; i < 2; i++) {
            float slo = 0.f, shi = 0.f;
            #pragma unroll
            for (int j = 0; j < 4; j++) {
                const int c = pass * BNP + wn * 32 + j * 8 + gc * 2;
                const float v0 = v_sh[c], v1 = v_sh[c + 1];
                const float q0 = q_sh[c], q1 = q_sh[c + 1];
                float x0 = q0 + acc[i][j][0], x1 = q1 + acc[i][j][1];
                float x2 = q0 + acc[i][j][2], x3 = q1 + acc[i][j][3];
                slo += v0 * (1.f - 2.f / (__expf(2.f * x0) + 1.f))
                     + v1 * (1.f - 2.f / (__expf(2.f * x1) + 1.f));
                shi += v0 * (1.f - 2.f / (__expf(2.f * x2) + 1.f))
                     + v1 * (1.f - 2.f / (__expf(2.f * x3) + 1.f));
                #pragma unroll
                for (int r = 0; r < 4; r++) acc[i][j][r] = 0.f;
            }
            slo += __shfl_xor_sync(0xffffffffu, slo, 1);
            slo += __shfl_xor_sync(0xffffffffu, slo, 2);
            shi += __shfl_xor_sync(0xffffffffu, shi, 1);
            shi += __shfl_xor_sync(0xffffffffu, shi, 2);
            if (gc == 0) {
                atomicAdd(&score_sm[wm * 32 + i * 16 + gr], slo);
                atomicAdd(&score_sm[wm * 32 + i * 16 + gr + 8], shi);
            }
        }
    }

    __syncthreads();
    if (tid < BM)
        g_scores[(size_t)b * SEQ + l0 + tid] = score_sm[tid];
}

// ---------------------------------------------------------------------------
// Kernel 3: softmax over L per batch; zero-inits the context region of out.
// ---------------------------------------------------------------------------
__global__ void softmax_kernel(float* __restrict__ out) {
    __shared__ float sm[SEQ];
    __shared__ float red[256];
    const int b = blockIdx.x, tid = threadIdx.x;

    for (int d = tid; d < DIM; d += 256) out[b * DIM + d] = 0.f;

    float m = -1e30f;
    for (int l = tid; l < SEQ; l += 256) {
        float s = g_scores[b * SEQ + l];
        sm[l] = s;
        m = fmaxf(m, s);
    }
    red[tid] = m;
    __syncthreads();
    for (int o = 128; o; o >>= 1) {
        if (tid < o) red[tid] = fmaxf(red[tid], red[tid + o]);
        __syncthreads();
    }
    m = red[0];
    __syncthreads();

    float sum = 0.f;
    for (int l = tid; l < SEQ; l += 256) {
        float e = __expf(sm[l] - m);
        sm[l] = e;
        sum += e;
    }
    red[tid] = sum;
    __syncthreads();
    for (int o = 128; o; o >>= 1) {
        if (tid < o) red[tid] += red[tid + o];
        __syncthreads();
    }
    const float inv = 1.f / red[0];

    float* attn = out + BATCH * DIM;
    for (int l = tid; l < SEQ; l += 256) attn[b * SEQ + l] = sm[l] * inv;
}

// ---------------------------------------------------------------------------
// Kernel 4: context[b,d] += sum_{l in chunk} attn[b,l] * enc_h[b,l,d]
// fp16 enc (written by score), fp32 accumulate + atomicAdd.
// Grid (BATCH, 32): 64 rows/block.
// ---------------------------------------------------------------------------
__global__ void context_kernel(float* __restrict__ out) {
    __shared__ float attn_sm[64];
    const int b = blockIdx.x, ch = blockIdx.y, tid = threadIdx.x;
    const int lbase = ch * 64;
    if (tid < 64) attn_sm[tid] = out[BATCH * DIM + (size_t)b * SEQ + lbase + tid];
    __syncthreads();

    float acc0 = 0.f, acc1 = 0.f, acc2 = 0.f, acc3 = 0.f;
    const __half* ep = g_enc_h + ((size_t)b * SEQ + lbase) * DIM + tid * 4;
    #pragma unroll 8
    for (int l = 0; l < 64; ++l) {
        float a = attn_sm[l];
        uint2 raw = *(const uint2*)(ep + (size_t)l * DIM);
        __half2 h0 = *(__half2*)&raw.x, h1 = *(__half2*)&raw.y;
        float2 f0 = __half22float2(h0), f1 = __half22float2(h1);
        acc0 += a * f0.x; acc1 += a * f0.y;
        acc2 += a * f1.x; acc3 += a * f1.y;
    }
    float* dst = out + b * DIM + tid * 4;
    atomicAdd(dst + 0, acc0);
    atomicAdd(dst + 1, acc1);
    atomicAdd(dst + 2, acc2);
    atomicAdd(dst + 3, acc3);
}

// ---------------------------------------------------------------------------
extern "C" void kernel_launch(void* const* d_in, const int* in_sizes, int n_in,
                              void* d_out, int out_size) {
    const float* dh  = (const float*)d_in[0];   // [32,1,1024]
    const float* enc = (const float*)d_in[1];   // [32,2048,1024]
    const float* Ww  = (const float*)d_in[2];   // [1024,1024]
    const float* Wb  = (const float*)d_in[3];   // [1024]
    const float* Uw  = (const float*)d_in[4];   // [1024,1024]
    const float* Ub  = (const float*)d_in[5];   // [1024]
    const float* vw  = (const float*)d_in[6];   // [1,1024]
    float* out = (float*)d_out;                 // [32768 context | 65536 attn]

    (void)in_sizes; (void)n_in; (void)out_size;

    static bool attr_set = false;
    if (!attr_set) {
        cudaFuncSetAttribute(score_kernel,
                             cudaFuncAttributeMaxDynamicSharedMemorySize, SMEM_BYTES);
        attr_set = true;
    }

    prep_kernel<<<NUCONV_BLOCKS + NQP_BLOCKS, 256>>>(Uw, dh, Ww, Wb, Ub);

    dim3 sgrid(SEQ / BM, BATCH);   // (32, 32) = 1024 blocks
    score_kernel<<<sgrid, 256, SMEM_BYTES>>>(enc, vw);

    softmax_kernel<<<BATCH, 256>>>(out);

    dim3 cgrid(BATCH, 32);
    context_kernel<<<cgrid, 256>>>(out);
}